// round 1
// baseline (speedup 1.0000x reference)
#include <cuda_runtime.h>
#include <math.h>

// Problem constants
#define BB    8
#define AA    512
#define NBH   64
#define FD    128
#define GD    50
// padded shared strides (bank-conflict control)
#define NSTR  132   // s_nbh row stride (16B aligned: 132*4=528)
#define PSTR  132   // s_pt  row stride
#define USTR  136   // s_u   row stride (544 bytes, 16B aligned)

__device__ int g_mask_u8;

// Detect whether the mask buffer is 1-byte bools or 4-byte (int32/float32)
// values. For 4-byte 0/1 values (little-endian) every byte at offset
// (i % 4 == 1) is zero; for 1-byte random bools ~50% are nonzero.
// Deterministic given the inputs.
__global__ void detect_mask_kernel(const unsigned char* __restrict__ m) {
    __shared__ int found;
    if (threadIdx.x == 0) found = 0;
    __syncthreads();
    int acc = 0;
    for (int i = threadIdx.x * 4 + 1; i < 8192; i += blockDim.x * 4)
        if (m[i]) acc = 1;
    if (acc) atomicOr(&found, 1);
    __syncthreads();
    if (threadIdx.x == 0) g_mask_u8 = found;
}

__global__ __launch_bounds__(256)
void tdt_kernel(const float* __restrict__ x,
                const float* __restrict__ r_ij,
                const float* __restrict__ f_ij,
                const float* __restrict__ Wf,
                const float* __restrict__ bfilt,
                const float* __restrict__ Wq,
                const float* __restrict__ Wk,
                const float* __restrict__ Wv,
                const float* __restrict__ Wo,
                const float* __restrict__ bo,
                const int*   __restrict__ nbr,
                const void*  __restrict__ maskp,
                float*       __restrict__ out)
{
    __shared__ float s_nbh[NBH * NSTR];   // filter-modulated gathered neighbors
    __shared__ float s_pt[8 * PSTR];      // p^T[h][j] = (Wk q)^T
    __shared__ float s_u[8 * USTR];       // u[h][j] = attn-weighted nbh
    __shared__ float s_sc[8 * NBH];       // scores -> attn (in place)
    __shared__ float s_q[FD];
    __shared__ float s_xa[FD];
    __shared__ float s_m[FD];
    __shared__ float s_C[NBH];
    __shared__ int   s_nb[NBH];
    __shared__ int   s_mk[NBH];

    const int tid  = threadIdx.x;
    const int atom = blockIdx.x;           // b*512 + a
    const int b    = atom >> 9;
    const float* xb  = x + (size_t)b * (AA * FD);
    const size_t an  = (size_t)atom * NBH;
    const float* fij = f_ij + an * GD;
    const int u8 = g_mask_u8;

    // ---- phase A: loads ----
    if (tid < FD) s_xa[tid] = x[(size_t)atom * FD + tid];
    if (tid >= 128 && tid < 192) {
        int n = tid - 128;
        float r = r_ij[an + n];
        s_C[n]  = (r < 5.0f) ? 0.5f * (cospif(r * 0.2f) + 1.0f) : 0.0f;
        s_nb[n] = nbr[an + n];
        int mv;
        if (u8) mv = ((const unsigned char*)maskp)[an + n];
        else    mv = ((const int*)maskp)[an + n];
        s_mk[n] = (mv != 0);
    }
    __syncthreads();

    // ---- q = x_a @ Wq (128 outputs) ----
    if (tid < FD) {
        float acc = 0.f;
        #pragma unroll 8
        for (int j = 0; j < FD; ++j) acc += s_xa[j] * Wq[j * FD + tid];
        s_q[tid] = acc;
    }
    __syncthreads();

    // ---- p^T[h][j] = sum_d Wk[j][h*16+d] * q[h*16+d] ----
    for (int o = tid; o < 1024; o += 256) {
        int j = o & 127, h = o >> 7;      // thread covers 4 h values for its j
        const float* wr = Wk + j * FD + h * 16;
        const float* qq = s_q + h * 16;
        float acc = 0.f;
        #pragma unroll
        for (int d = 0; d < 16; ++d) acc += wr[d] * qq[d];
        s_pt[h * PSTR + j] = acc;
    }

    // ---- filter GEMM (64x128x50) + cutoff + gather multiply -> s_nbh ----
    {
        const int ft = tid & 15, nt = tid >> 4;
        const int f0 = ft * 8, n0 = nt * 4;
        float bf8[8];
        #pragma unroll
        for (int jj = 0; jj < 8; ++jj) bf8[jj] = bfilt[f0 + jj];
        float acc[4][8];
        #pragma unroll
        for (int i = 0; i < 4; ++i)
            #pragma unroll
            for (int jj = 0; jj < 8; ++jj) acc[i][jj] = bf8[jj];

        const float* f0p = fij + (size_t)n0 * GD;
        for (int g = 0; g < GD; ++g) {
            float w[8];
            *(float4*)(w)     = *(const float4*)(Wf + g * FD + f0);
            *(float4*)(w + 4) = *(const float4*)(Wf + g * FD + f0 + 4);
            float a[4];
            a[0] = f0p[0 * GD + g];
            a[1] = f0p[1 * GD + g];
            a[2] = f0p[2 * GD + g];
            a[3] = f0p[3 * GD + g];
            #pragma unroll
            for (int i = 0; i < 4; ++i)
                #pragma unroll
                for (int jj = 0; jj < 8; ++jj)
                    acc[i][jj] += a[i] * w[jj];
        }

        #pragma unroll
        for (int i = 0; i < 4; ++i) {
            const int n = n0 + i;
            const float c = s_C[n];
            const float* xg = xb + (size_t)s_nb[n] * FD + f0;
            float gg[8];
            *(float4*)(gg)     = *(const float4*)xg;
            *(float4*)(gg + 4) = *(const float4*)(xg + 4);
            float res[8];
            #pragma unroll
            for (int jj = 0; jj < 8; ++jj) res[jj] = acc[i][jj] * gg[jj] * c;
            float* dst = s_nbh + n * NSTR + f0;
            *(float4*)(dst)     = *(float4*)(res);
            *(float4*)(dst + 4) = *(float4*)(res + 4);
        }
    }
    __syncthreads();

    // ---- scores[h][n] = (sum_j nbh[n][j] * p[h][j]) * 0.25, masked ----
    {
        const int n = tid & 63, hp = tid >> 6;     // hp in 0..3, handles h=hp and h=hp+4
        const float* row = s_nbh + n * NSTR;
        const float* pa  = s_pt + hp * PSTR;
        const float* pb  = s_pt + (hp + 4) * PSTR;
        float a0 = 0.f, a1 = 0.f;
        #pragma unroll 4
        for (int j = 0; j < FD; j += 4) {
            float4 v  = *(const float4*)(row + j);
            float4 qa = *(const float4*)(pa + j);
            float4 qb = *(const float4*)(pb + j);
            a0 += v.x * qa.x + v.y * qa.y + v.z * qa.z + v.w * qa.w;
            a1 += v.x * qb.x + v.y * qb.y + v.z * qb.z + v.w * qb.w;
        }
        const bool m = (s_mk[n] != 0);
        s_sc[hp * 64 + n]       = m ? a0 * 0.25f : -1e9f;
        s_sc[(hp + 4) * 64 + n] = m ? a1 * 0.25f : -1e9f;
    }
    __syncthreads();

    // ---- softmax over n, one warp per head ----
    {
        const int h = tid >> 5, lane = tid & 31;
        float* sc = s_sc + h * 64;
        float v0 = sc[lane], v1 = sc[lane + 32];
        float mx = fmaxf(v0, v1);
        #pragma unroll
        for (int o = 16; o > 0; o >>= 1)
            mx = fmaxf(mx, __shfl_xor_sync(0xffffffffu, mx, o));
        float e0 = __expf(v0 - mx), e1 = __expf(v1 - mx);
        float s = e0 + e1;
        #pragma unroll
        for (int o = 16; o > 0; o >>= 1)
            s += __shfl_xor_sync(0xffffffffu, s, o);
        float inv = 1.0f / s;
        sc[lane] = e0 * inv;
        sc[lane + 32] = e1 * inv;
    }
    __syncthreads();

    // ---- u[h][j] = sum_n attn[h][n] * nbh[n][j], one warp per head ----
    {
        const int h = tid >> 5, lane = tid & 31;
        const float* at = s_sc + h * 64;
        float4 acc = make_float4(0.f, 0.f, 0.f, 0.f);
        #pragma unroll 4
        for (int n = 0; n < NBH; ++n) {
            const float a = at[n];
            float4 v = *(const float4*)(s_nbh + n * NSTR + lane * 4);
            acc.x += a * v.x; acc.y += a * v.y; acc.z += a * v.z; acc.w += a * v.w;
        }
        *(float4*)(s_u + h * USTR + lane * 4) = acc;
    }
    __syncthreads();

    // ---- msg[f] = sum_j u[h(f)][j] * Wv[j][f] ----
    if (tid < FD) {
        const int h = tid >> 4;
        const float* u = s_u + h * USTR;
        float acc = 0.f;
        #pragma unroll 8
        for (int j = 0; j < FD; ++j) acc += u[j] * Wv[j * FD + tid];
        s_m[tid] = acc;
    }
    __syncthreads();

    // ---- out[f] = x[f] + bo[f] + sum_j msg[j] * Wo[j][f] ----
    if (tid < FD) {
        float acc = bo[tid];
        #pragma unroll 8
        for (int j = 0; j < FD; ++j) acc += s_m[j] * Wo[j * FD + tid];
        out[(size_t)atom * FD + tid] = s_xa[tid] + acc;
    }
}

extern "C" void kernel_launch(void* const* d_in, const int* in_sizes, int n_in,
                              void* d_out, int out_size)
{
    // metadata order: e, x, t, r_ij, f_ij, W_filt, b_filt, Wq, Wk, Wv, Wo, bo,
    //                 neighbors, neighbor_mask     (e and t are unused)
    const float* x    = (const float*)d_in[1];
    const float* r    = (const float*)d_in[3];
    const float* fij  = (const float*)d_in[4];
    const float* Wf   = (const float*)d_in[5];
    const float* bf   = (const float*)d_in[6];
    const float* Wq   = (const float*)d_in[7];
    const float* Wk   = (const float*)d_in[8];
    const float* Wv   = (const float*)d_in[9];
    const float* Wo   = (const float*)d_in[10];
    const float* bo   = (const float*)d_in[11];
    const int*   nbr  = (const int*)d_in[12];
    const void*  mk   = d_in[13];

    detect_mask_kernel<<<1, 256>>>((const unsigned char*)mk);
    tdt_kernel<<<BB * AA, 256>>>(x, r, fij, Wf, bf, Wq, Wk, Wv, Wo, bo,
                                 nbr, mk, (float*)d_out);
}

// round 3
// speedup vs baseline: 1.3289x; 1.3289x over previous
#include <cuda_runtime.h>
#include <math.h>

// Problem constants
#define BB    8
#define AA    512
#define NBH   64
#define FD    128
#define GD    50
// padded shared strides
#define NSTR  132   // s_nbh row stride (528B, 16B aligned, conflict-free both ways)
#define PSTR  132
#define USTR  136
#define FSTR  52    // s_fij row stride

typedef unsigned long long u64;

__device__ __forceinline__ void fma2(u64 &d, u64 a, u64 b) {
    asm("fma.rn.f32x2 %0, %1, %2, %0;" : "+l"(d) : "l"(a), "l"(b));
}
__device__ __forceinline__ u64 pk2(float lo, float hi) {
    u64 r; asm("mov.b64 %0, {%1, %2};" : "=l"(r) : "f"(lo), "f"(hi)); return r;
}
__device__ __forceinline__ float2 upk2(u64 v) {
    float2 t; asm("mov.b64 {%0, %1}, %2;" : "=f"(t.x), "=f"(t.y) : "l"(v)); return t;
}
__device__ __forceinline__ u64 mul2_(u64 a, u64 b) {
    u64 r; asm("mul.rn.f32x2 %0, %1, %2;" : "=l"(r) : "l"(a), "l"(b)); return r;
}

__device__ int g_mask_u8;

// Detect 1-byte bool vs 4-byte int mask (deterministic).
__global__ void detect_mask_kernel(const unsigned char* __restrict__ m) {
    __shared__ int found;
    if (threadIdx.x == 0) found = 0;
    __syncthreads();
    int acc = 0;
    for (int i = threadIdx.x * 4 + 1; i < 8192; i += blockDim.x * 4)
        if (m[i]) acc = 1;
    if (acc) atomicOr(&found, 1);
    __syncthreads();
    if (threadIdx.x == 0) g_mask_u8 = found;
}

__global__ __launch_bounds__(256)
void tdt_kernel(const float* __restrict__ x,
                const float* __restrict__ r_ij,
                const float* __restrict__ f_ij,
                const float* __restrict__ Wf,
                const float* __restrict__ bfilt,
                const float* __restrict__ Wq,
                const float* __restrict__ Wk,
                const float* __restrict__ Wv,
                const float* __restrict__ Wo,
                const float* __restrict__ bo,
                const int*   __restrict__ nbr,
                const void*  __restrict__ maskp,
                float*       __restrict__ out)
{
    __shared__ __align__(16) float s_nbh[NBH * NSTR];   // 33792 f
    __shared__ __align__(16) float s_pt[8 * PSTR];      // p^T[h][j]
    __shared__ __align__(16) float s_un[NBH * FSTR];    // union: s_fij | (s_u, s_sc, s_m)
    __shared__ __align__(16) float s_q[FD];
    __shared__ __align__(16) float s_xa[FD];
    __shared__ float s_C[NBH];
    __shared__ int   s_nb[NBH];
    __shared__ int   s_mk[NBH];

    float* const s_fij = s_un;                 // epoch 1 (filter)
    float* const s_u   = s_un;                 // epoch 2: 8*USTR = 1088 f
    float* const s_sc  = s_un + 8 * USTR;      // 512 f
    float* const s_m   = s_un + 8 * USTR + 512;// 128 f

    const int tid  = threadIdx.x;
    const int atom = blockIdx.x;
    const int b    = atom >> 9;
    const float* xb  = x + (size_t)b * (AA * FD);
    const size_t an  = (size_t)atom * NBH;
    const float* fij = f_ij + an * GD;
    const int u8 = g_mask_u8;

    // ---- P0: stage loads ----
    for (int i = tid; i < NBH * GD; i += 256) {
        int r = i / GD, c = i - r * GD;
        s_fij[r * FSTR + c] = fij[i];
    }
    if (tid < FD) s_xa[tid] = x[(size_t)atom * FD + tid];
    if (tid >= 128 && tid < 192) {
        int n = tid - 128;
        float r = r_ij[an + n];
        s_C[n]  = (r < 5.0f) ? 0.5f * (cospif(r * 0.2f) + 1.0f) : 0.0f;
        s_nb[n] = nbr[an + n];
        int mv;
        if (u8) mv = ((const unsigned char*)maskp)[an + n];
        else    mv = ((const int*)maskp)[an + n];
        s_mk[n] = (mv != 0);
    }
    __syncthreads();

    // ---- P1: q = x_a @ Wq ----
    if (tid < FD) {
        float a0 = 0.f, a1 = 0.f;
        #pragma unroll 8
        for (int j = 0; j < FD; j += 2) {
            a0 += s_xa[j]     * Wq[j * FD + tid];
            a1 += s_xa[j + 1] * Wq[(j + 1) * FD + tid];
        }
        s_q[tid] = a0 + a1;
    }
    __syncthreads();

    // ---- P2a: p^T[h][j] = sum_d Wk[j][h*16+d]*q[h*16+d]  (coalesced rows) ----
    {
        const int j  = tid >> 1;
        const int hh = (tid & 1) * 4;
        const float* wr = Wk + j * FD + hh * 16;
        #pragma unroll
        for (int hi = 0; hi < 4; ++hi) {
            const int h = hh + hi;
            const u64* wv = (const u64*)(wr + hi * 16);
            const u64* qv = (const u64*)(s_q + h * 16);
            u64 a0 = 0ull, a1 = 0ull;
            #pragma unroll
            for (int p = 0; p < 8; p += 2) {
                fma2(a0, wv[p],     qv[p]);
                fma2(a1, wv[p + 1], qv[p + 1]);
            }
            float2 r0 = upk2(a0), r1 = upk2(a1);
            s_pt[h * PSTR + j] = (r0.x + r0.y) + (r1.x + r1.y);
        }
    }

    // ---- P2b: filter GEMM (64x128x50) + cutoff + gather -> s_nbh (f32x2) ----
    {
        const int ft = tid & 15, nt = tid >> 4;
        const int f0 = ft * 8, n0 = nt * 4;
        u64 acc[4][4];
        {
            ulonglong2 bA = *(const ulonglong2*)(bfilt + f0);
            ulonglong2 bB = *(const ulonglong2*)(bfilt + f0 + 4);
            #pragma unroll
            for (int i = 0; i < 4; ++i) {
                acc[i][0] = bA.x; acc[i][1] = bA.y;
                acc[i][2] = bB.x; acc[i][3] = bB.y;
            }
        }
        const float* fr = s_fij + n0 * FSTR;
        #pragma unroll 2
        for (int g = 0; g < GD; ++g) {
            ulonglong2 wA = *(const ulonglong2*)(Wf + g * FD + f0);
            ulonglong2 wB = *(const ulonglong2*)(Wf + g * FD + f0 + 4);
            u64 w2[4] = { wA.x, wA.y, wB.x, wB.y };
            u64 a2[4];
            #pragma unroll
            for (int i = 0; i < 4; ++i) {
                float a = fr[i * FSTR + g];
                a2[i] = pk2(a, a);
            }
            #pragma unroll
            for (int i = 0; i < 4; ++i)
                #pragma unroll
                for (int jj = 0; jj < 4; ++jj)
                    fma2(acc[i][jj], a2[i], w2[jj]);
        }
        #pragma unroll
        for (int i = 0; i < 4; ++i) {
            const int n = n0 + i;
            const float c = s_C[n];
            const u64 c2 = pk2(c, c);
            const float* xg = xb + (size_t)s_nb[n] * FD + f0;
            ulonglong2 gA = *(const ulonglong2*)(xg);
            ulonglong2 gB = *(const ulonglong2*)(xg + 4);
            ulonglong2 rA, rB;
            rA.x = mul2_(mul2_(acc[i][0], gA.x), c2);
            rA.y = mul2_(mul2_(acc[i][1], gA.y), c2);
            rB.x = mul2_(mul2_(acc[i][2], gB.x), c2);
            rB.y = mul2_(mul2_(acc[i][3], gB.y), c2);
            *(ulonglong2*)(s_nbh + n * NSTR + f0)     = rA;
            *(ulonglong2*)(s_nbh + n * NSTR + f0 + 4) = rB;
        }
    }
    __syncthreads();

    // ---- P3: scores[h][n] (f32x2), masked ----
    {
        const int n = tid & 63, hp = tid >> 6;   // heads hp and hp+4
        const float* row = s_nbh + n * NSTR;
        const float* pa  = s_pt + hp * PSTR;
        const float* pb  = s_pt + (hp + 4) * PSTR;
        u64 A0 = 0ull, A1 = 0ull, B0 = 0ull, B1 = 0ull;
        #pragma unroll 4
        for (int j = 0; j < FD; j += 8) {
            ulonglong2 v0 = *(const ulonglong2*)(row + j);
            ulonglong2 v1 = *(const ulonglong2*)(row + j + 4);
            ulonglong2 qa0 = *(const ulonglong2*)(pa + j);
            ulonglong2 qa1 = *(const ulonglong2*)(pa + j + 4);
            ulonglong2 qb0 = *(const ulonglong2*)(pb + j);
            ulonglong2 qb1 = *(const ulonglong2*)(pb + j + 4);
            fma2(A0, v0.x, qa0.x); fma2(A1, v0.y, qa0.y);
            fma2(A0, v1.x, qa1.x); fma2(A1, v1.y, qa1.y);
            fma2(B0, v0.x, qb0.x); fma2(B1, v0.y, qb0.y);
            fma2(B0, v1.x, qb1.x); fma2(B1, v1.y, qb1.y);
        }
        float2 a0 = upk2(A0), a1 = upk2(A1), b0 = upk2(B0), b1 = upk2(B1);
        float sa = (a0.x + a0.y) + (a1.x + a1.y);
        float sb = (b0.x + b0.y) + (b1.x + b1.y);
        const bool m = (s_mk[n] != 0);
        s_sc[hp * 64 + n]       = m ? sa * 0.25f : -1e9f;
        s_sc[(hp + 4) * 64 + n] = m ? sb * 0.25f : -1e9f;
    }
    __syncthreads();

    // ---- P4: softmax, one warp per head ----
    {
        const int h = tid >> 5, lane = tid & 31;
        float* sc = s_sc + h * 64;
        float v0 = sc[lane], v1 = sc[lane + 32];
        float mx = fmaxf(v0, v1);
        #pragma unroll
        for (int o = 16; o > 0; o >>= 1)
            mx = fmaxf(mx, __shfl_xor_sync(0xffffffffu, mx, o));
        float e0 = __expf(v0 - mx), e1 = __expf(v1 - mx);
        float s = e0 + e1;
        #pragma unroll
        for (int o = 16; o > 0; o >>= 1)
            s += __shfl_xor_sync(0xffffffffu, s, o);
        float inv = 1.0f / s;
        sc[lane] = e0 * inv;
        sc[lane + 32] = e1 * inv;
    }
    __syncthreads();

    // ---- P5: u[h][j] = sum_n attn[h][n]*nbh[n][j] (f32x2) ----
    {
        const int h = tid >> 5, lane = tid & 31;
        const float* at = s_sc + h * 64;
        u64 a0 = 0ull, a1 = 0ull;
        #pragma unroll 4
        for (int n = 0; n < NBH; ++n) {
            u64 av = pk2(at[n], at[n]);
            ulonglong2 v = *(const ulonglong2*)(s_nbh + n * NSTR + lane * 4);
            fma2(a0, av, v.x);
            fma2(a1, av, v.y);
        }
        ulonglong2 r; r.x = a0; r.y = a1;
        *(ulonglong2*)(s_u + h * USTR + lane * 4) = r;
    }
    __syncthreads();

    // ---- P6: msg[f] = sum_j u[h(f)][j]*Wv[j][f] ----
    if (tid < FD) {
        const int h = tid >> 4;
        const float* u = s_u + h * USTR;
        float a0 = 0.f, a1 = 0.f;
        #pragma unroll 8
        for (int j = 0; j < FD; j += 2) {
            a0 += u[j]     * Wv[j * FD + tid];
            a1 += u[j + 1] * Wv[(j + 1) * FD + tid];
        }
        s_m[tid] = a0 + a1;
    }
    __syncthreads();

    // ---- P7: out[f] = x[f] + bo[f] + sum_j msg[j]*Wo[j][f] ----
    if (tid < FD) {
        float a0 = bo[tid], a1 = 0.f;
        #pragma unroll 8
        for (int j = 0; j < FD; j += 2) {
            a0 += s_m[j]     * Wo[j * FD + tid];
            a1 += s_m[j + 1] * Wo[(j + 1) * FD + tid];
        }
        out[(size_t)atom * FD + tid] = s_xa[tid] + a0 + a1;
    }
}

extern "C" void kernel_launch(void* const* d_in, const int* in_sizes, int n_in,
                              void* d_out, int out_size)
{
    // metadata order: e, x, t, r_ij, f_ij, W_filt, b_filt, Wq, Wk, Wv, Wo, bo,
    //                 neighbors, neighbor_mask     (e and t are unused)
    const float* x    = (const float*)d_in[1];
    const float* r    = (const float*)d_in[3];
    const float* fij  = (const float*)d_in[4];
    const float* Wf   = (const float*)d_in[5];
    const float* bf   = (const float*)d_in[6];
    const float* Wq   = (const float*)d_in[7];
    const float* Wk   = (const float*)d_in[8];
    const float* Wv   = (const float*)d_in[9];
    const float* Wo   = (const float*)d_in[10];
    const float* bo   = (const float*)d_in[11];
    const int*   nbr  = (const int*)d_in[12];
    const void*  mk   = d_in[13];

    detect_mask_kernel<<<1, 256>>>((const unsigned char*)mk);
    tdt_kernel<<<BB * AA, 256>>>(x, r, fij, Wf, bf, Wq, Wk, Wv, Wo, bo,
                                 nbr, mk, (float*)d_out);
}